// round 1
// baseline (speedup 1.0000x reference)
#include <cuda_runtime.h>
#include <math.h>

#define NT      262144      // total nodes (512 subgraphs x 512 nodes)
#define NN      512         // nodes per subgraph / original graph
#define NS      512         // number of subgraphs
#define E_SUB   2097152     // edges in union-of-subgraphs graph
#define EO      8192        // edges in original graph
#define D       64          // emb dim
#define LAYERS  4

// ------------------------- device scratch (no cudaMalloc allowed) ----------
__device__ __align__(16) float g_hA[(size_t)NT * D];
__device__ __align__(16) float g_hB[(size_t)NT * D];
__device__ __align__(16) float g_agg[(size_t)NT * D];

__device__ __align__(16) float g_xsum[NN * D];
__device__ __align__(16) float g_aggs[NN * D];
__device__ __align__(16) float g_y2[NN * D];

__device__ __align__(16) float g_stA[2 * D];      // [0:64) colsum, [64:128) colsumsq (big BN)
__device__ __align__(16) float g_stS[2 * D];      // same for subgraph BN
__device__ __align__(16) float g_scale[D],  g_shift[D];
__device__ __align__(16) float g_scale_s[D], g_shift_s[D];

__device__ int g_cnt[NT];          // counts, then reused as scatter cursor
__device__ int g_rowptr[NT + 1];
__device__ int g_bsum[256];
__device__ int g_csrsrc[E_SUB];

// ------------------------- CSR build ---------------------------------------
__global__ void k_hist(const int* __restrict__ dst) {
    int e = blockIdx.x * blockDim.x + threadIdx.x;
    if (e < E_SUB) atomicAdd(&g_cnt[dst[e]], 1);
}

__global__ void k_bsum() {
    __shared__ int sh[256];
    int b = blockIdx.x, t = threadIdx.x;
    int base = b * 1024 + t * 4;
    int v = g_cnt[base] + g_cnt[base + 1] + g_cnt[base + 2] + g_cnt[base + 3];
    sh[t] = v;
    __syncthreads();
    for (int off = 128; off > 0; off >>= 1) {
        if (t < off) sh[t] += sh[t + off];
        __syncthreads();
    }
    if (t == 0) g_bsum[b] = sh[0];
}

__global__ void k_scanb() {
    __shared__ int sh[256];
    int t = threadIdx.x;
    int orig = g_bsum[t];
    sh[t] = orig;
    __syncthreads();
    for (int off = 1; off < 256; off <<= 1) {
        int v = (t >= off) ? sh[t - off] : 0;
        __syncthreads();
        sh[t] += v;
        __syncthreads();
    }
    g_bsum[t] = sh[t] - orig;   // exclusive
}

__global__ void k_scanlocal() {
    __shared__ int sh[256];
    int b = blockIdx.x, t = threadIdx.x;
    int base = (b * 256 + t) * 4;
    int c0 = g_cnt[base], c1 = g_cnt[base + 1], c2 = g_cnt[base + 2], c3 = g_cnt[base + 3];
    int tsum = c0 + c1 + c2 + c3;
    sh[t] = tsum;
    __syncthreads();
    for (int off = 1; off < 256; off <<= 1) {
        int v = (t >= off) ? sh[t - off] : 0;
        __syncthreads();
        sh[t] += v;
        __syncthreads();
    }
    int excl = sh[t] - tsum + g_bsum[b];
    int e0 = excl, e1 = e0 + c0, e2 = e1 + c1, e3 = e2 + c2;
    g_rowptr[base] = e0; g_rowptr[base + 1] = e1;
    g_rowptr[base + 2] = e2; g_rowptr[base + 3] = e3;
    g_cnt[base] = e0; g_cnt[base + 1] = e1;     // cursor init
    g_cnt[base + 2] = e2; g_cnt[base + 3] = e3;
    if (b == 255 && t == 255) g_rowptr[NT] = E_SUB;
}

__global__ void k_scatter(const int* __restrict__ src, const int* __restrict__ dst) {
    int e = blockIdx.x * blockDim.x + threadIdx.x;
    if (e < E_SUB) {
        int pos = atomicAdd(&g_cnt[dst[e]], 1);
        g_csrsrc[pos] = src[e];
    }
}

// ------------------------- edge aggregation (atomic-free) ------------------
__global__ void k_gather(const float* __restrict__ h) {
    int gw = (blockIdx.x * blockDim.x + threadIdx.x) >> 5;
    int lane = threadIdx.x & 31;
    if (gw >= NT) return;
    int s = g_rowptr[gw], e = g_rowptr[gw + 1];
    float a0 = 0.f, a1 = 0.f, b0 = 0.f, b1 = 0.f;
    int i = s;
    for (; i + 1 < e; i += 2) {
        int s0 = g_csrsrc[i], s1 = g_csrsrc[i + 1];
        const float* p0 = h + (size_t)s0 * D;
        const float* p1 = h + (size_t)s1 * D;
        a0 += p0[lane]; a1 += p0[lane + 32];
        b0 += p1[lane]; b1 += p1[lane + 32];
    }
    if (i < e) {
        int s0 = g_csrsrc[i];
        const float* p0 = h + (size_t)s0 * D;
        a0 += p0[lane]; a1 += p0[lane + 32];
    }
    g_agg[(size_t)gw * D + lane]      = a0 + b0;
    g_agg[(size_t)gw * D + lane + 32] = a1 + b1;
}

// ------------------------- dual GEMM: Y = A0@W0^T + A1@W1^T + bias ---------
__global__ void __launch_bounds__(256)
k_gemm(const float* __restrict__ A0, const float* __restrict__ A1,
       const float* __restrict__ W0, const float* __restrict__ W1v,
       const float* __restrict__ bias, float* __restrict__ Y) {
    __shared__ __align__(16) float sA[64][65];   // sA[k][row]
    __shared__ __align__(16) float sW[64][68];   // sW[k][col], pitch 68 keeps float4 alignment
    int t  = threadIdx.x;
    int tx = t & 15, ty = t >> 4;
    int row0 = blockIdx.x * 64;
    int cc = t & 63, rb = t >> 6;

    float acc[4][4];
#pragma unroll
    for (int i = 0; i < 4; i++)
#pragma unroll
        for (int j = 0; j < 4; j++) acc[i][j] = 0.f;

    for (int p = 0; p < 2; p++) {
        const float* A = p ? A1 : A0;
        const float* W = p ? W1v : W0;
#pragma unroll
        for (int j = 0; j < 16; j++) {
            int r = rb + j * 4;
            sA[cc][r] = A[(size_t)(row0 + r) * D + cc];      // transpose store, pitch 65: conflict-free
        }
#pragma unroll
        for (int j = 0; j < 16; j++) {
            int ci = rb + j * 4;
            sW[cc][ci] = W[ci * D + cc];                     // W[c][k] -> sW[k][c]
        }
        __syncthreads();
#pragma unroll
        for (int k = 0; k < 64; k++) {
            float4 bv = *reinterpret_cast<const float4*>(&sW[k][tx * 4]);
            float a0 = sA[k][ty * 4 + 0];
            float a1 = sA[k][ty * 4 + 1];
            float a2 = sA[k][ty * 4 + 2];
            float a3 = sA[k][ty * 4 + 3];
            acc[0][0] += a0 * bv.x; acc[0][1] += a0 * bv.y; acc[0][2] += a0 * bv.z; acc[0][3] += a0 * bv.w;
            acc[1][0] += a1 * bv.x; acc[1][1] += a1 * bv.y; acc[1][2] += a1 * bv.z; acc[1][3] += a1 * bv.w;
            acc[2][0] += a2 * bv.x; acc[2][1] += a2 * bv.y; acc[2][2] += a2 * bv.z; acc[2][3] += a2 * bv.w;
            acc[3][0] += a3 * bv.x; acc[3][1] += a3 * bv.y; acc[3][2] += a3 * bv.z; acc[3][3] += a3 * bv.w;
        }
        __syncthreads();
    }
    float4 bb = *reinterpret_cast<const float4*>(&bias[tx * 4]);
#pragma unroll
    for (int jr = 0; jr < 4; jr++) {
        int r = row0 + ty * 4 + jr;
        float4 o = make_float4(acc[jr][0] + bb.x, acc[jr][1] + bb.y,
                               acc[jr][2] + bb.z, acc[jr][3] + bb.w);
        *reinterpret_cast<float4*>(&Y[(size_t)r * D + tx * 4]) = o;
    }
}

// ------------------------- BN stats + finalize ------------------------------
__global__ void k_stats(const float* __restrict__ Y, int rpb, float* __restrict__ st) {
    int b = blockIdx.x, t = threadIdx.x;
    int c = t & 63, j = t >> 6;
    float s = 0.f, s2 = 0.f;
    int r0 = b * rpb;
    for (int r = r0 + j; r < r0 + rpb; r += 4) {
        float v = Y[(size_t)r * D + c];
        s += v; s2 += v * v;
    }
    __shared__ float sh[256], sh2[256];
    sh[t] = s; sh2[t] = s2;
    __syncthreads();
    if (t < 64) {
        float ts = sh[t] + sh[64 + t] + sh[128 + t] + sh[192 + t];
        float t2 = sh2[t] + sh2[64 + t] + sh2[128 + t] + sh2[192 + t];
        atomicAdd(&st[t], ts);
        atomicAdd(&st[64 + t], t2);
    }
}

__global__ void k_finalize(const float* __restrict__ st,
                           const float* __restrict__ gamma, const float* __restrict__ beta,
                           float inv, float* __restrict__ scale, float* __restrict__ shift) {
    int t = threadIdx.x;
    float mean = st[t] * inv;
    float var  = st[64 + t] * inv - mean * mean;
    float is   = rsqrtf(var + 1e-5f);
    float sc   = gamma[t] * is;
    scale[t] = sc;
    shift[t] = beta[t] - mean * sc;
}

// ------------------------- subgraph mean (x_sum) ----------------------------
__global__ void k_xsum_partial(const float* __restrict__ h) {
    int n  = blockIdx.x & (NN - 1);
    int sg = blockIdx.x >> 9;
    int c  = threadIdx.x;
    float a0 = 0.f, a1 = 0.f, a2 = 0.f, a3 = 0.f;
#pragma unroll 4
    for (int j = 0; j < 64; j += 4) {
        int s = sg * 64 + j;
        a0 += h[((size_t)(s + 0) * NN + n) * D + c];
        a1 += h[((size_t)(s + 1) * NN + n) * D + c];
        a2 += h[((size_t)(s + 2) * NN + n) * D + c];
        a3 += h[((size_t)(s + 3) * NN + n) * D + c];
    }
    atomicAdd(&g_xsum[n * D + c], (a0 + a1 + a2 + a3) * (1.0f / 512.0f));
}

// ------------------------- small graph scatter ------------------------------
__global__ void k_scatter_s(const int* __restrict__ src, const int* __restrict__ dst) {
    int t = blockIdx.x * blockDim.x + threadIdx.x;
    int e = t >> 6, c = t & 63;
    if (e < EO) atomicAdd(&g_aggs[dst[e] * D + c], g_xsum[src[e] * D + c]);
}

// ------------------------- combine: h = relu(BN1(y) + BN2(y2)[n]) ----------
__global__ void k_combine(float* __restrict__ Y) {
    int i4 = blockIdx.x * blockDim.x + threadIdx.x;     // < NT*16
    int r = i4 >> 4, q = i4 & 15;
    int n = r & (NN - 1);
    int cb = q * 4;
    float4 y   = reinterpret_cast<float4*>(Y)[i4];
    float4 sc  = *reinterpret_cast<const float4*>(&g_scale[cb]);
    float4 sf  = *reinterpret_cast<const float4*>(&g_shift[cb]);
    float4 scs = *reinterpret_cast<const float4*>(&g_scale_s[cb]);
    float4 sfs = *reinterpret_cast<const float4*>(&g_shift_s[cb]);
    float4 y2  = *reinterpret_cast<const float4*>(&g_y2[n * D + cb]);
    y.x = fmaxf(y.x * sc.x + sf.x + y2.x * scs.x + sfs.x, 0.f);
    y.y = fmaxf(y.y * sc.y + sf.y + y2.y * scs.y + sfs.y, 0.f);
    y.z = fmaxf(y.z * sc.z + sf.z + y2.z * scs.z + sfs.z, 0.f);
    y.w = fmaxf(y.w * sc.w + sf.w + y2.w * scs.w + sfs.w, 0.f);
    reinterpret_cast<float4*>(Y)[i4] = y;
}

// ------------------------- final head: log_softmax + MLP -------------------
__global__ void k_final(const float* __restrict__ W1, const float* __restrict__ b1,
                        const float* __restrict__ W2, const float* __restrict__ b2,
                        float* __restrict__ out) {
    __shared__ float z[64];
    __shared__ float hid[128];
    __shared__ float red[2];
    int n = blockIdx.x, t = threadIdx.x;
    if (t < 64) z[t] = g_xsum[n * D + t];
    __syncthreads();
    if (t == 0) {
        float m = -1e30f;
        for (int k = 0; k < 64; k++) m = fmaxf(m, z[k]);
        float se = 0.f;
        for (int k = 0; k < 64; k++) se += expf(z[k] - m);
        red[0] = m;
        red[1] = logf(se);
    }
    __syncthreads();
    float m = red[0], ls = red[1];
    float acc = b1[t];
    for (int k = 0; k < 64; k++) acc += (z[k] - m - ls) * W1[t * 64 + k];
    hid[t] = fmaxf(acc, 0.f);
    __syncthreads();
    if (t < 10) {
        float o = b2[t];
        for (int k = 0; k < 128; k++) o += hid[k] * W2[t * 128 + k];
        out[n * 10 + t] = o;
    }
}

// ------------------------- launcher -----------------------------------------
extern "C" void kernel_launch(void* const* d_in, const int* in_sizes, int n_in,
                              void* d_out, int out_size) {
    const float* x      = (const float*)d_in[0];
    const float* Wrel   = (const float*)d_in[1];
    const float* brel   = (const float*)d_in[2];
    const float* Wroot  = (const float*)d_in[3];
    const float* bng    = (const float*)d_in[4];
    const float* bnb    = (const float*)d_in[5];
    const float* Wrel_s = (const float*)d_in[6];
    const float* brel_s = (const float*)d_in[7];
    const float* Wroot_s= (const float*)d_in[8];
    const float* bnsg   = (const float*)d_in[9];
    const float* bnsb   = (const float*)d_in[10];
    const float* W1     = (const float*)d_in[11];
    const float* b1     = (const float*)d_in[12];
    const float* W2     = (const float*)d_in[13];
    const float* b2     = (const float*)d_in[14];
    const int*   ei     = (const int*)d_in[15];
    const int*   oe     = (const int*)d_in[16];
    float*       out    = (float*)d_out;

    void *p_cnt, *p_hA, *p_hB, *p_agg, *p_xsum, *p_aggs, *p_y2;
    void *p_stA, *p_stS, *p_scale, *p_shift, *p_scale_s, *p_shift_s;
    cudaGetSymbolAddress(&p_cnt, g_cnt);
    cudaGetSymbolAddress(&p_hA, g_hA);
    cudaGetSymbolAddress(&p_hB, g_hB);
    cudaGetSymbolAddress(&p_agg, g_agg);
    cudaGetSymbolAddress(&p_xsum, g_xsum);
    cudaGetSymbolAddress(&p_aggs, g_aggs);
    cudaGetSymbolAddress(&p_y2, g_y2);
    cudaGetSymbolAddress(&p_stA, g_stA);
    cudaGetSymbolAddress(&p_stS, g_stS);
    cudaGetSymbolAddress(&p_scale, g_scale);
    cudaGetSymbolAddress(&p_shift, g_shift);
    cudaGetSymbolAddress(&p_scale_s, g_scale_s);
    cudaGetSymbolAddress(&p_shift_s, g_shift_s);

    // ---- CSR build (per replay; edge list is constant but sort is cheap) ----
    cudaMemsetAsync(p_cnt, 0, NT * sizeof(int));
    k_hist<<<E_SUB / 256, 256>>>(ei + E_SUB);
    k_bsum<<<256, 256>>>();
    k_scanb<<<1, 256>>>();
    k_scanlocal<<<256, 256>>>();
    k_scatter<<<E_SUB / 256, 256>>>(ei, ei + E_SUB);

    const float* hcur = x;
    float* bufs[2] = { (float*)p_hA, (float*)p_hB };

    for (int i = 0; i < LAYERS; i++) {
        float* Y = bufs[i & 1];

        // big-graph path: aggregation + dual GEMM + BN stats
        k_gather<<<(NT * 32) / 256, 256>>>(hcur);
        k_gemm<<<NT / 64, 256>>>((const float*)p_agg, hcur,
                                 Wrel + i * 4096, Wroot + i * 4096, brel + i * 64, Y);
        cudaMemsetAsync(p_stA, 0, 2 * D * sizeof(float));
        k_stats<<<1024, 256>>>(Y, NT / 1024, (float*)p_stA);
        k_finalize<<<1, 64>>>((const float*)p_stA, bng + i * 64, bnb + i * 64,
                              1.0f / (float)NT, (float*)p_scale, (float*)p_shift);

        // subgraph-level path
        cudaMemsetAsync(p_xsum, 0, NN * D * sizeof(float));
        k_xsum_partial<<<NN * 8, 64>>>(hcur);
        cudaMemsetAsync(p_aggs, 0, NN * D * sizeof(float));
        k_scatter_s<<<(EO * 64) / 256, 256>>>(oe, oe + EO);
        k_gemm<<<NN / 64, 256>>>((const float*)p_aggs, (const float*)p_xsum,
                                 Wrel_s + i * 4096, Wroot_s + i * 4096, brel_s + i * 64,
                                 (float*)p_y2);
        cudaMemsetAsync(p_stS, 0, 2 * D * sizeof(float));
        k_stats<<<8, 256>>>((const float*)p_y2, NN / 8, (float*)p_stS);
        k_finalize<<<1, 64>>>((const float*)p_stS, bnsg + i * 64, bnsb + i * 64,
                              1.0f / (float)NN, (float*)p_scale_s, (float*)p_shift_s);

        // fuse both BNs + broadcast + relu, in place
        k_combine<<<(NT * 16) / 256, 256>>>(Y);
        hcur = Y;
    }

    // readout: subgraph mean -> log_softmax -> MLP
    cudaMemsetAsync(p_xsum, 0, NN * D * sizeof(float));
    k_xsum_partial<<<NN * 8, 64>>>(hcur);
    k_final<<<NN, 128>>>(W1, b1, W2, b2, out);
}